// round 13
// baseline (speedup 1.0000x reference)
#include <cuda_runtime.h>
#include <cstdint>
#include <cstddef>

#define NVEC 1024
#define NDIM 64
#define NHID 32
#define NW   10
#define NB   16
#define NOFF 11

// Scratch (no allocations allowed): device globals.
// g_w layout: [i][b][og(3)][n][4]  (11 offsets padded to 12, grouped by 4)
__device__ float g_w[NW * NB * 3 * NVEC * 4];
__device__ float g_H[NW * NB * NVEC * NHID];   // gelu hidden activations (21MB)
__device__ float g_fW2T[NW * NVEC * NHID];     // fW2 transposed [i][n][h]
__device__ float g_fWT3[10 * 16 * NVEC * 4];   // finW as [c][dg][n][4] (2.6MB)
__device__ float g_part[NB * 16 * 10];         // partial sums for output GEMM
__device__ int   g_cnt;                        // block completion counter

// ---------- f32x2 packed helpers (sm_103a FFMA2) ----------
__device__ __forceinline__ unsigned long long pack2(float x, float y) {
    unsigned long long r;
    asm("mov.b64 %0, {%1, %2};" : "=l"(r) : "f"(x), "f"(y));
    return r;
}
__device__ __forceinline__ void fma2(unsigned long long& d, unsigned long long a, unsigned long long b) {
    asm("fma.rn.f32x2 %0, %1, %2, %0;" : "+l"(d) : "l"(a), "l"(b));
}
__device__ __forceinline__ float2 unpack2(unsigned long long v) {
    float lo, hi;
    asm("mov.b64 {%0, %1}, %2;" : "=f"(lo), "=f"(hi) : "l"(v));
    return make_float2(lo, hi);
}
// Fast gelu: A&S 7.1.26 erf approximation, |abs err| <= 1.5e-7 (vs 1e-3 budget).
__device__ __forceinline__ float gelu_exact(float x) {
    float az = fabsf(x) * 0.70710678118f;                 // |x|/sqrt(2)
    float t  = __fdividef(1.0f, fmaf(0.3275911f, az, 1.0f));
    float p  = fmaf(t, 1.061405429f, -1.453152027f);
    p = fmaf(t, p, 1.421413741f);
    p = fmaf(t, p, -0.284496736f);
    p = fmaf(t, p, 0.254829592f);
    p *= t;
    float e = __expf(-az * az);
    float erfz = fmaf(-p, e, 1.0f);                       // erf(|z|)
    float s = copysignf(erfz, x);
    return 0.5f * x * (1.0f + s);
}

// ---------------------------------------------------------------------------
// Kernel A: H = gelu(X @ fW1 + fb1), 4n x 8h register tile, 128 THREADS,
// n-tile 128, 8 CTAs/SM (64 regs x 128 x 8 = 64K regs; 25.7KB smem x 8).
// Fine-grained blocks kill the wave-quantization tail (1280 blocks / 1184 cap).
// X pre-duplicated (Xs[128][34]) -> FFMA2 a-operand is one LDS.64.
// z == 10: transpose fW2 -> g_fW2T.   z == 11: finW -> g_fWT3.
// ---------------------------------------------------------------------------
#define XS 34
#define H_SMEM ((128 * XS + NDIM * NHID + NHID) * 4)   // 25728 B

__global__ void __launch_bounds__(128, 8) h_kernel(
    const float* __restrict__ data, const float* __restrict__ fW1,
    const float* __restrict__ fb1,  const float* __restrict__ fW2,
    const float* __restrict__ finW)
{
    extern __shared__ float sm[];
    const int t = threadIdx.x;

    // ---------------- fW2 transpose branch ----------------
    if (blockIdx.z == NW) {
        int idx = blockIdx.y * 8 + blockIdx.x;     // 0..127
        if (idx >= 2 * NW) return;
        const int i  = idx >> 1;
        const int c0 = (idx & 1) * 512;
        float* tile = sm;                          // [32][33]
        for (int s = 0; s < 16; s++) {
#pragma unroll
            for (int it = 0; it < 8; it++) {       // 32 rows x 32 cols, 128 thr
                int r = it * 4 + (t >> 5);
                int c = t & 31;
                tile[r * 33 + c] = fW2[((size_t)(i * NHID) + r) * NVEC + c0 + s * 32 + c];
            }
            __syncthreads();
#pragma unroll
            for (int it2 = 0; it2 < 2; it2++) {    // 256 outputs, 128 thr
                int tt = t + 128 * it2;
                int cr = tt >> 3, rg = tt & 7;
                float4 v = make_float4(tile[(4 * rg + 0) * 33 + cr],
                                       tile[(4 * rg + 1) * 33 + cr],
                                       tile[(4 * rg + 2) * 33 + cr],
                                       tile[(4 * rg + 3) * 33 + cr]);
                *reinterpret_cast<float4*>(
                    &g_fW2T[((size_t)(i * NVEC) + c0 + s * 32 + cr) * NHID + 4 * rg]) = v;
            }
            __syncthreads();
        }
        return;
    }

    // ------------- finW transpose branch: [f][10] -> [c][dg][n][4] ----------
    if (blockIdx.z == NW + 1) {
        int idx = blockIdx.y * 8 + blockIdx.x;     // 0..127
        if (idx >= 32) return;
        float* sF = sm;                            // [256][11]
        float4* dst = reinterpret_cast<float4*>(g_fWT3);
#pragma unroll 1
        for (int s = 0; s < 8; s++) {              // 8 sub-tiles of 256 f
            const int fbase = idx * 2048 + s * 256;
            const int nbase = idx * 32 + s * 4;
            const float4* src =
                reinterpret_cast<const float4*>(finW + (size_t)fbase * 10);
#pragma unroll
            for (int j = 0; j < 5; j++) {          // 640 float4
                int p = t + 128 * j;
                float4 v = __ldg(src + p);
                float vals[4] = {v.x, v.y, v.z, v.w};
#pragma unroll
                for (int u = 0; u < 4; u++) {
                    int e  = 4 * p + u;
                    int fl = e / 10, c = e - 10 * fl;
                    sF[fl * 11 + c] = vals[u];
                }
            }
            __syncthreads();
#pragma unroll
            for (int j = 0; j < 5; j++) {          // 640 outputs
                int oi = t + 128 * j;
                int c  = oi / 64;
                int r  = oi - 64 * c;
                int dg = r >> 2, nn = r & 3;
                float4 v;
                v.x = sF[(nn * 64 + 4 * dg + 0) * 11 + c];
                v.y = sF[(nn * 64 + 4 * dg + 1) * 11 + c];
                v.z = sF[(nn * 64 + 4 * dg + 2) * 11 + c];
                v.w = sF[(nn * 64 + 4 * dg + 3) * 11 + c];
                dst[(c * 16 + dg) * 1024 + nbase + nn] = v;
            }
            __syncthreads();
        }
        return;
    }

    // ---------------- H branch (n-tile = 128 rows) ----------------
    float* Xs   = sm;                   // [128][34] duplicated pairs
    float* sw1  = Xs + 128 * XS;        // [64][32]
    float* sfb1 = sw1 + NDIM * NHID;    // [32]

    const int n0 = blockIdx.x * 128;
    const int b  = blockIdx.y;
    const int i  = blockIdx.z;

    for (int idx = t; idx < NDIM * NHID; idx += 128)
        sw1[idx] = fW1[i * NDIM * NHID + idx];
    if (t < NHID) sfb1[t] = fb1[i * NHID + t];

    const int ht8 = (t & 3) * 8;
    const int nb  = (t >> 2) * 4;       // 32 groups x 4 rows = 128
    const float4* src =
        reinterpret_cast<const float4*>(data + ((size_t)b * NVEC + n0) * NDIM);
    const unsigned long long* Xu =
        reinterpret_cast<const unsigned long long*>(Xs);   // row stride 17 ull

    unsigned long long acc[4][4];
#pragma unroll
    for (int j = 0; j < 4; j++)
#pragma unroll
        for (int p = 0; p < 4; p++) acc[j][p] = 0ull;

#pragma unroll 1
    for (int c = 0; c < 4; c++) {
        // stage chunk c (128 rows x 16 k = 512 float4) as duplicated pairs
#pragma unroll
        for (int j = 0; j < 4; j++) {
            int q   = t + 128 * j;
            int row = q >> 2, sub = q & 3;
            float4 v = __ldg(src + row * 16 + c * 4 + sub);
            unsigned long long* d = reinterpret_cast<unsigned long long*>(
                Xs + row * XS + sub * 8);
            d[0] = pack2(v.x, v.x);
            d[1] = pack2(v.y, v.y);
            d[2] = pack2(v.z, v.z);
            d[3] = pack2(v.w, v.w);
        }
        __syncthreads();

#pragma unroll
        for (int kk = 0; kk < 16; kk++) {
            int k = 16 * c + kk;
            const ulonglong2* wp =
                reinterpret_cast<const ulonglong2*>(&sw1[k * NHID + ht8]);
            ulonglong2 wA = wp[0];
            ulonglong2 wB = wp[1];
#pragma unroll
            for (int j = 0; j < 4; j++) {
                unsigned long long xx = Xu[(nb + j) * 17 + kk];  // LDS.64
                fma2(acc[j][0], xx, wA.x);
                fma2(acc[j][1], xx, wA.y);
                fma2(acc[j][2], xx, wB.x);
                fma2(acc[j][3], xx, wB.y);
            }
        }
        if (c < 3) __syncthreads();
    }

    const unsigned long long* bp =
        reinterpret_cast<const unsigned long long*>(&sfb1[ht8]);
    float2 bb[4];
#pragma unroll
    for (int p = 0; p < 4; p++) bb[p] = unpack2(bp[p]);

    float* Hbase = g_H + ((size_t)(i * NB + b) * NVEC) * NHID;
#pragma unroll
    for (int j = 0; j < 4; j++) {
        float2 v0 = unpack2(acc[j][0]);
        float2 v1 = unpack2(acc[j][1]);
        float2 v2 = unpack2(acc[j][2]);
        float2 v3 = unpack2(acc[j][3]);
        float4 a = make_float4(gelu_exact(v0.x + bb[0].x), gelu_exact(v0.y + bb[0].y),
                               gelu_exact(v1.x + bb[1].x), gelu_exact(v1.y + bb[1].y));
        float4 cc = make_float4(gelu_exact(v2.x + bb[2].x), gelu_exact(v2.y + bb[2].y),
                                gelu_exact(v3.x + bb[3].x), gelu_exact(v3.y + bb[3].y));
        float* dst = Hbase + (size_t)(n0 + nb + j) * NHID + ht8;
        reinterpret_cast<float4*>(dst)[0] = a;
        reinterpret_cast<float4*>(dst)[1] = cc;
    }
}

// ---------------------------------------------------------------------------
// Kernel B: sparse W values. Block = (b, i), 1024 threads (t = n), 160 blocks.
// Results gathered in registers, then written as 3 coalesced STG.128.
// ---------------------------------------------------------------------------
#define FTS 36
#define W2_SMEM ((NVEC * FTS + NVEC) * 4)   // 151552 B

__global__ void __launch_bounds__(1024) w2_kernel(const float* __restrict__ fb2)
{
    extern __shared__ float sm[];
    float* sfT  = sm;              // [1024][36]
    float* sfb2 = sm + NVEC * FTS; // [1024]

    const int t = threadIdx.x;
    const int b = blockIdx.x;
    const int i = blockIdx.y;

    const float4* src4 =
        reinterpret_cast<const float4*>(g_fW2T + (size_t)i * NVEC * NHID);
#pragma unroll
    for (int q = 0; q < 8; q++) {
        int p = t + 1024 * q;
        float4 v = src4[p];
        int n = p >> 3, c = (p & 7) << 2;
        *reinterpret_cast<float4*>(&sfT[n * FTS + c]) = v;
    }
    sfb2[t] = __ldg(&fb2[i * NVEC + t]);

    float h[32];
    {
        const float4* hp = reinterpret_cast<const float4*>(
            g_H + ((size_t)(i * NB + b) * NVEC + t) * NHID);
#pragma unroll
        for (int q = 0; q < 8; q++) {
            float4 v = __ldg(hp + q);
            h[4 * q] = v.x; h[4 * q + 1] = v.y; h[4 * q + 2] = v.z; h[4 * q + 3] = v.w;
        }
    }
    __syncthreads();

    const int OFF[NOFF] = {0, 1, 2, 4, 8, 16, 32, 64, 128, 256, 512};
    float wres[12];
#pragma unroll
    for (int o = 0; o < NOFF; o++) {
        int m = (t + OFF[o]) & (NVEC - 1);
        const float4* rp = reinterpret_cast<const float4*>(&sfT[m * FTS]);
        float s0 = 0.f, s1 = 0.f, s2 = 0.f, s3 = 0.f;
#pragma unroll
        for (int q = 0; q < 8; q++) {
            float4 w = rp[q];
            s0 = fmaf(h[4 * q],     w.x, s0);
            s1 = fmaf(h[4 * q + 1], w.y, s1);
            s2 = fmaf(h[4 * q + 2], w.z, s2);
            s3 = fmaf(h[4 * q + 3], w.w, s3);
        }
        wres[o] = (s0 + s1) + (s2 + s3) + sfb2[m];
    }
    wres[11] = 0.f;

    float4* dst = reinterpret_cast<float4*>(g_w) + ((size_t)(i * NB + b) * 3) * NVEC + t;
    dst[0]        = make_float4(wres[0], wres[1], wres[2],  wres[3]);
    dst[NVEC]     = make_float4(wres[4], wres[5], wres[6],  wres[7]);
    dst[2 * NVEC] = make_float4(wres[8], wres[9], wres[10], wres[11]);
}

// ---------------------------------------------------------------------------
// Kernel 2: 10-layer sparse recursion, vectorized (block = (dg,b) owns 4 dims
// as float4). 256 blocks, 2 CTAs/SM. Per-layer w fetch = 3 coalesced LDG.128
// (prefetched one layer ahead). Fused output-GEMM epilogue.
// ---------------------------------------------------------------------------
__global__ void __launch_bounds__(1024, 2) recurse_kernel(
    const float* __restrict__ data, const float* __restrict__ finb,
    float* __restrict__ out)
{
    __shared__ float4 Vs[2][NVEC];
    __shared__ int isLast;
    const int t  = threadIdx.x;
    const int dg = blockIdx.x;
    const int b  = blockIdx.y;

    float4 acc = __ldg(reinterpret_cast<const float4*>(
        data + ((size_t)(b * NVEC) + t) * NDIM + 4 * dg));
    Vs[0][t] = acc;

    const int OFF[NOFF] = {0, 1, 2, 4, 8, 16, 32, 64, 128, 256, 512};
    const float4* Wv = reinterpret_cast<const float4*>(g_w);

    float4 wq0, wq1, wq2;
    {
        size_t base = ((size_t)(9 * NB + b) * 3) * NVEC + t;
        wq0 = __ldg(&Wv[base]);
        wq1 = __ldg(&Wv[base + NVEC]);
        wq2 = __ldg(&Wv[base + 2 * NVEC]);
    }
    __syncthreads();

    int cur = 0;
#pragma unroll
    for (int i = NW - 1; i >= 0; i--) {
        float4 nq0, nq1, nq2;
        if (i > 0) {
            size_t base = ((size_t)((i - 1) * NB + b) * 3) * NVEC + t;
            nq0 = __ldg(&Wv[base]);
            nq1 = __ldg(&Wv[base + NVEC]);
            nq2 = __ldg(&Wv[base + 2 * NVEC]);
        }
        float wv[NOFF] = {wq0.x, wq0.y, wq0.z, wq0.w,
                          wq1.x, wq1.y, wq1.z, wq1.w,
                          wq2.x, wq2.y, wq2.z};

        float4 na;
        na.x = fmaf(wv[0], acc.x, acc.x);
        na.y = fmaf(wv[0], acc.y, acc.y);
        na.z = fmaf(wv[0], acc.z, acc.z);
        na.w = fmaf(wv[0], acc.w, acc.w);
#pragma unroll
        for (int o = 1; o < NOFF; o++) {
            int m = (t + OFF[o]) & (NVEC - 1);
            float4 v = Vs[cur][m];
            na.x = fmaf(wv[o], v.x, na.x);
            na.y = fmaf(wv[o], v.y, na.y);
            na.z = fmaf(wv[o], v.z, na.z);
            na.w = fmaf(wv[o], v.w, na.w);
        }
        Vs[cur ^ 1][t] = na;
        acc = na;
        __syncthreads();
        cur ^= 1;
        wq0 = nq0; wq1 = nq1; wq2 = nq2;
    }

    const float4* W3 = reinterpret_cast<const float4*>(g_fWT3);
    float cs[10];
#pragma unroll
    for (int c = 0; c < 10; c++) {
        float4 w = __ldg(&W3[(c * 16 + dg) * 1024 + t]);
        cs[c] = acc.x * w.x + acc.y * w.y + acc.z * w.z + acc.w * w.w;
    }

#pragma unroll
    for (int c = 0; c < 10; c++) {
#pragma unroll
        for (int s = 16; s > 0; s >>= 1)
            cs[c] += __shfl_xor_sync(0xffffffffu, cs[c], s);
    }
    float* red = reinterpret_cast<float*>(&Vs[0][0]);
    int lane = t & 31, wp = t >> 5;
    if (lane == 0) {
#pragma unroll
        for (int c = 0; c < 10; c++) red[wp * 10 + c] = cs[c];
    }
    __syncthreads();
    if (t < 10) {
        float s = 0.f;
        for (int w_ = 0; w_ < 32; w_++) s += red[w_ * 10 + t];
        g_part[(b * 16 + dg) * 10 + t] = s;
    }
    __threadfence();
    if (t == 0) {
        int old = atomicAdd(&g_cnt, 1);
        isLast = (old == NB * 16 - 1);
    }
    __syncthreads();
    if (isLast) {
        __threadfence();
        if (t == 0) g_cnt = 0;
        if (t < NB * 10) {
            int bb = t / 10, c = t - bb * 10;
            float s = __ldg(&finb[c]);
#pragma unroll
            for (int cc = 0; cc < 16; cc++) s += g_part[(bb * 16 + cc) * 10 + c];
            out[t] = s;
        }
    }
}

// ---------------------------------------------------------------------------
extern "C" void kernel_launch(void* const* d_in, const int* in_sizes, int n_in,
                              void* d_out, int out_size)
{
    const float* data = (const float*)d_in[0];
    const float* fW1  = (const float*)d_in[1];
    const float* fb1  = (const float*)d_in[2];
    const float* fW2  = (const float*)d_in[3];
    const float* fb2  = (const float*)d_in[4];
    const float* finW = (const float*)d_in[5];
    const float* finb = (const float*)d_in[6];
    float* out = (float*)d_out;

    cudaFuncSetAttribute(h_kernel,
                         cudaFuncAttributeMaxDynamicSharedMemorySize, H_SMEM);
    cudaFuncSetAttribute(w2_kernel,
                         cudaFuncAttributeMaxDynamicSharedMemorySize, W2_SMEM);

    h_kernel<<<dim3(8, 16, 12), 128, H_SMEM>>>(data, fW1, fb1, fW2, finW);
    w2_kernel<<<dim3(16, 10), 1024, W2_SMEM>>>(fb2);
    recurse_kernel<<<dim3(16, 16), 1024>>>(data, finb, out);
}

// round 14
// speedup vs baseline: 1.0653x; 1.0653x over previous
#include <cuda_runtime.h>
#include <cstdint>
#include <cstddef>

#define NVEC 1024
#define NDIM 64
#define NHID 32
#define NW   10
#define NB   16
#define NOFF 11

// Scratch (no allocations allowed): device globals.
__device__ float g_w[NW * NB * NOFF * NVEC];   // sparse W values [i][b][o][n]
__device__ float g_H[NW * NB * NVEC * NHID];   // gelu hidden activations (21MB)
__device__ float g_fW2T[NW * NVEC * NHID];     // fW2 transposed [i][n][h]
__device__ float g_fWT3[10 * 16 * NVEC * 4];   // finW as [c][dg][n][4] (2.6MB)
__device__ float g_part[NB * 16 * 10];         // partial sums for output GEMM
__device__ int   g_cnt;                        // block completion counter

// ---------- f32x2 packed helpers (sm_103a FFMA2) ----------
__device__ __forceinline__ unsigned long long pack2(float x, float y) {
    unsigned long long r;
    asm("mov.b64 %0, {%1, %2};" : "=l"(r) : "f"(x), "f"(y));
    return r;
}
__device__ __forceinline__ void fma2(unsigned long long& d, unsigned long long a, unsigned long long b) {
    asm("fma.rn.f32x2 %0, %1, %2, %0;" : "+l"(d) : "l"(a), "l"(b));
}
__device__ __forceinline__ float2 unpack2(unsigned long long v) {
    float lo, hi;
    asm("mov.b64 {%0, %1}, %2;" : "=f"(lo), "=f"(hi) : "l"(v));
    return make_float2(lo, hi);
}
// Fast gelu: A&S 7.1.26 erf approximation, |abs err| <= 1.5e-7 (vs 1e-3 budget).
__device__ __forceinline__ float gelu_exact(float x) {
    float az = fabsf(x) * 0.70710678118f;                 // |x|/sqrt(2)
    float t  = __fdividef(1.0f, fmaf(0.3275911f, az, 1.0f));
    float p  = fmaf(t, 1.061405429f, -1.453152027f);
    p = fmaf(t, p, 1.421413741f);
    p = fmaf(t, p, -0.284496736f);
    p = fmaf(t, p, 0.254829592f);
    p *= t;
    float e = __expf(-az * az);
    float erfz = fmaf(-p, e, 1.0f);                       // erf(|z|)
    float s = copysignf(erfz, x);
    return 0.5f * x * (1.0f + s);
}

// ---------------------------------------------------------------------------
// Kernel A (R9 config): H = gelu(X @ fW1 + fb1), 4n x 8h register tile,
// 256 threads, k CHUNKED (4 x 16) -> Xs[256][17], 25.7KB smem, 4 CTAs/SM.
// z == 10: transpose fW2 -> g_fW2T.   z == 11: finW -> g_fWT3 (4 sub-tiles).
// ---------------------------------------------------------------------------
#define XS 17
#define H_SMEM ((256 * XS + NDIM * NHID + NHID) * 4)   // 25728 B

__global__ void __launch_bounds__(256, 4) h_kernel(
    const float* __restrict__ data, const float* __restrict__ fW1,
    const float* __restrict__ fb1,  const float* __restrict__ fW2,
    const float* __restrict__ finW)
{
    extern __shared__ float sm[];
    const int t = threadIdx.x;

    // ---------------- fW2 transpose branch ----------------
    if (blockIdx.z == NW) {
        int idx = blockIdx.y * 4 + blockIdx.x;     // 0..63
        if (idx >= 2 * NW) return;
        const int i  = idx >> 1;
        const int c0 = (idx & 1) * 512;
        float* tile = sm;                          // [32][33]
        for (int s = 0; s < 16; s++) {
#pragma unroll
            for (int it = 0; it < 4; it++) {
                int r = it * 8 + (t >> 5);
                int c = t & 31;
                if (r < 32)
                    tile[r * 33 + c] = fW2[((size_t)(i * NHID) + r) * NVEC + c0 + s * 32 + c];
            }
            __syncthreads();
            int cr = t >> 3, rg = t & 7;
            float4 v = make_float4(tile[(4 * rg + 0) * 33 + cr],
                                   tile[(4 * rg + 1) * 33 + cr],
                                   tile[(4 * rg + 2) * 33 + cr],
                                   tile[(4 * rg + 3) * 33 + cr]);
            *reinterpret_cast<float4*>(
                &g_fW2T[((size_t)(i * NVEC) + c0 + s * 32 + cr) * NHID + 4 * rg]) = v;
            __syncthreads();
        }
        return;
    }

    // ------------- finW transpose branch: [f][10] -> [c][dg][n][4] ----------
    if (blockIdx.z == NW + 1) {
        int idx = blockIdx.y * 4 + blockIdx.x;     // 0..63
        float* sF = sm;                            // [256][11]
        float4* dst = reinterpret_cast<float4*>(g_fWT3);
#pragma unroll 1
        for (int s = 0; s < 4; s++) {
            const int fbase = idx * 1024 + s * 256;
            const int nbase = (idx * 16) + s * 4;
            const float4* src =
                reinterpret_cast<const float4*>(finW + (size_t)fbase * 10);
#pragma unroll
            for (int j = 0; j < 3; j++) {
                int p = t + 256 * j;
                if (p < 640) {
                    float4 v = __ldg(src + p);
                    float vals[4] = {v.x, v.y, v.z, v.w};
#pragma unroll
                    for (int u = 0; u < 4; u++) {
                        int e  = 4 * p + u;
                        int fl = e / 10, c = e - 10 * fl;
                        sF[fl * 11 + c] = vals[u];
                    }
                }
            }
            __syncthreads();
#pragma unroll
            for (int j = 0; j < 3; j++) {
                int oi = t + 256 * j;
                if (oi < 640) {
                    int c  = oi / 64;
                    int r  = oi - 64 * c;
                    int dg = r >> 2, nn = r & 3;
                    float4 v;
                    v.x = sF[(nn * 64 + 4 * dg + 0) * 11 + c];
                    v.y = sF[(nn * 64 + 4 * dg + 1) * 11 + c];
                    v.z = sF[(nn * 64 + 4 * dg + 2) * 11 + c];
                    v.w = sF[(nn * 64 + 4 * dg + 3) * 11 + c];
                    dst[(c * 16 + dg) * 1024 + nbase + nn] = v;
                }
            }
            __syncthreads();
        }
        return;
    }

    // ---------------- H branch ----------------
    float* Xs   = sm;                   // [256][17]
    float* sw1  = Xs + 256 * XS;        // [64][32]
    float* sfb1 = sw1 + NDIM * NHID;    // [32]

    const int n0 = blockIdx.x * 256;
    const int b  = blockIdx.y;
    const int i  = blockIdx.z;

    for (int idx = t; idx < NDIM * NHID; idx += 256)
        sw1[idx] = fW1[i * NDIM * NHID + idx];
    if (t < NHID) sfb1[t] = fb1[i * NHID + t];

    const int ht8 = (t & 3) * 8;
    const int nb  = (t >> 2) * 4;
    const float4* src =
        reinterpret_cast<const float4*>(data + ((size_t)b * NVEC + n0) * NDIM);

    unsigned long long acc[4][4];
#pragma unroll
    for (int j = 0; j < 4; j++)
#pragma unroll
        for (int p = 0; p < 4; p++) acc[j][p] = 0ull;

#pragma unroll 1
    for (int c = 0; c < 4; c++) {
#pragma unroll
        for (int j = 0; j < 4; j++) {
            int q   = t + 256 * j;
            int row = q >> 2, sub = q & 3;
            float4 v = __ldg(src + row * 16 + c * 4 + sub);
            float* d = Xs + row * XS + sub * 4;
            d[0] = v.x; d[1] = v.y; d[2] = v.z; d[3] = v.w;
        }
        __syncthreads();

#pragma unroll
        for (int kk = 0; kk < 16; kk++) {
            int k = 16 * c + kk;
            const ulonglong2* wp =
                reinterpret_cast<const ulonglong2*>(&sw1[k * NHID + ht8]);
            ulonglong2 wA = wp[0];            // LDS.128
            ulonglong2 wB = wp[1];            // LDS.128
#pragma unroll
            for (int j = 0; j < 4; j++) {
                float xv = Xs[(nb + j) * XS + kk];
                unsigned long long xx = pack2(xv, xv);
                fma2(acc[j][0], xx, wA.x);
                fma2(acc[j][1], xx, wA.y);
                fma2(acc[j][2], xx, wB.x);
                fma2(acc[j][3], xx, wB.y);
            }
        }
        if (c < 3) __syncthreads();
    }

    const unsigned long long* bp =
        reinterpret_cast<const unsigned long long*>(&sfb1[ht8]);
    float2 bb[4];
#pragma unroll
    for (int p = 0; p < 4; p++) bb[p] = unpack2(bp[p]);

    float* Hbase = g_H + ((size_t)(i * NB + b) * NVEC) * NHID;
#pragma unroll
    for (int j = 0; j < 4; j++) {
        float2 v0 = unpack2(acc[j][0]);
        float2 v1 = unpack2(acc[j][1]);
        float2 v2 = unpack2(acc[j][2]);
        float2 v3 = unpack2(acc[j][3]);
        float4 a = make_float4(gelu_exact(v0.x + bb[0].x), gelu_exact(v0.y + bb[0].y),
                               gelu_exact(v1.x + bb[1].x), gelu_exact(v1.y + bb[1].y));
        float4 cc = make_float4(gelu_exact(v2.x + bb[2].x), gelu_exact(v2.y + bb[2].y),
                                gelu_exact(v3.x + bb[3].x), gelu_exact(v3.y + bb[3].y));
        float* dst = Hbase + (size_t)(n0 + nb + j) * NHID + ht8;
        reinterpret_cast<float4*>(dst)[0] = a;
        reinterpret_cast<float4*>(dst)[1] = cc;
    }
}

// ---------------------------------------------------------------------------
// Kernel B (R9 config): sparse W values. Block = (b, i), 1024 threads, 160 blocks.
// ---------------------------------------------------------------------------
#define FTS 36
#define W2_SMEM ((NVEC * FTS + NVEC) * 4)   // 151552 B

__global__ void __launch_bounds__(1024) w2_kernel(const float* __restrict__ fb2)
{
    extern __shared__ float sm[];
    float* sfT  = sm;              // [1024][36]
    float* sfb2 = sm + NVEC * FTS; // [1024]

    const int t = threadIdx.x;
    const int b = blockIdx.x;
    const int i = blockIdx.y;

    const float4* src4 =
        reinterpret_cast<const float4*>(g_fW2T + (size_t)i * NVEC * NHID);
#pragma unroll
    for (int q = 0; q < 8; q++) {
        int p = t + 1024 * q;
        float4 v = src4[p];
        int n = p >> 3, c = (p & 7) << 2;
        *reinterpret_cast<float4*>(&sfT[n * FTS + c]) = v;
    }
    sfb2[t] = __ldg(&fb2[i * NVEC + t]);

    float h[32];
    {
        const float4* hp = reinterpret_cast<const float4*>(
            g_H + ((size_t)(i * NB + b) * NVEC + t) * NHID);
#pragma unroll
        for (int q = 0; q < 8; q++) {
            float4 v = __ldg(hp + q);
            h[4 * q] = v.x; h[4 * q + 1] = v.y; h[4 * q + 2] = v.z; h[4 * q + 3] = v.w;
        }
    }
    __syncthreads();

    const int OFF[NOFF] = {0, 1, 2, 4, 8, 16, 32, 64, 128, 256, 512};
    float* out = g_w + (size_t)((i * NB + b) * NOFF) * NVEC + t;
#pragma unroll
    for (int o = 0; o < NOFF; o++) {
        int m = (t + OFF[o]) & (NVEC - 1);
        const float4* rp = reinterpret_cast<const float4*>(&sfT[m * FTS]);
        float s0 = 0.f, s1 = 0.f, s2 = 0.f, s3 = 0.f;
#pragma unroll
        for (int q = 0; q < 8; q++) {
            float4 w = rp[q];
            s0 = fmaf(h[4 * q],     w.x, s0);
            s1 = fmaf(h[4 * q + 1], w.y, s1);
            s2 = fmaf(h[4 * q + 2], w.z, s2);
            s3 = fmaf(h[4 * q + 3], w.w, s3);
        }
        out[(size_t)o * NVEC] = (s0 + s1) + (s2 + s3) + sfb2[m];
    }
}

// ---------------------------------------------------------------------------
// Kernel 2 (R9 config): 10-layer sparse recursion, vectorized (block = (dg,b)
// owns 4 dims as float4). 256 blocks, 2 CTAs/SM. Fused output-GEMM epilogue.
// ---------------------------------------------------------------------------
__global__ void __launch_bounds__(1024, 2) recurse_kernel(
    const float* __restrict__ data, const float* __restrict__ finb,
    float* __restrict__ out)
{
    __shared__ float4 Vs[2][NVEC];
    __shared__ int isLast;
    const int t  = threadIdx.x;
    const int dg = blockIdx.x;
    const int b  = blockIdx.y;

    float4 acc = __ldg(reinterpret_cast<const float4*>(
        data + ((size_t)(b * NVEC) + t) * NDIM + 4 * dg));
    Vs[0][t] = acc;

    const int OFF[NOFF] = {0, 1, 2, 4, 8, 16, 32, 64, 128, 256, 512};
    float wv[NOFF];
    {
        const float* w = g_w + (size_t)((9 * NB + b) * NOFF) * NVEC;
#pragma unroll
        for (int o = 0; o < NOFF; o++) wv[o] = __ldg(&w[o * NVEC + t]);
    }
    __syncthreads();

    int cur = 0;
#pragma unroll
    for (int i = NW - 1; i >= 0; i--) {
        float wn[NOFF];
        if (i > 0) {
            const float* w = g_w + (size_t)(((i - 1) * NB + b) * NOFF) * NVEC;
#pragma unroll
            for (int o = 0; o < NOFF; o++) wn[o] = __ldg(&w[o * NVEC + t]);
        }

        float4 na;
        na.x = fmaf(wv[0], acc.x, acc.x);
        na.y = fmaf(wv[0], acc.y, acc.y);
        na.z = fmaf(wv[0], acc.z, acc.z);
        na.w = fmaf(wv[0], acc.w, acc.w);
#pragma unroll
        for (int o = 1; o < NOFF; o++) {
            int m = (t + OFF[o]) & (NVEC - 1);
            float4 v = Vs[cur][m];
            na.x = fmaf(wv[o], v.x, na.x);
            na.y = fmaf(wv[o], v.y, na.y);
            na.z = fmaf(wv[o], v.z, na.z);
            na.w = fmaf(wv[o], v.w, na.w);
        }
        Vs[cur ^ 1][t] = na;
        acc = na;
        __syncthreads();
        cur ^= 1;
#pragma unroll
        for (int o = 0; o < NOFF; o++) wv[o] = wn[o];
    }

    const float4* W3 = reinterpret_cast<const float4*>(g_fWT3);
    float cs[10];
#pragma unroll
    for (int c = 0; c < 10; c++) {
        float4 w = __ldg(&W3[(c * 16 + dg) * 1024 + t]);
        cs[c] = acc.x * w.x + acc.y * w.y + acc.z * w.z + acc.w * w.w;
    }

#pragma unroll
    for (int c = 0; c < 10; c++) {
#pragma unroll
        for (int s = 16; s > 0; s >>= 1)
            cs[c] += __shfl_xor_sync(0xffffffffu, cs[c], s);
    }
    float* red = reinterpret_cast<float*>(&Vs[0][0]);
    int lane = t & 31, wp = t >> 5;
    if (lane == 0) {
#pragma unroll
        for (int c = 0; c < 10; c++) red[wp * 10 + c] = cs[c];
    }
    __syncthreads();
    if (t < 10) {
        float s = 0.f;
        for (int w_ = 0; w_ < 32; w_++) s += red[w_ * 10 + t];
        g_part[(b * 16 + dg) * 10 + t] = s;
    }
    __threadfence();
    if (t == 0) {
        int old = atomicAdd(&g_cnt, 1);
        isLast = (old == NB * 16 - 1);
    }
    __syncthreads();
    if (isLast) {
        __threadfence();
        if (t == 0) g_cnt = 0;
        if (t < NB * 10) {
            int bb = t / 10, c = t - bb * 10;
            float s = __ldg(&finb[c]);
#pragma unroll
            for (int cc = 0; cc < 16; cc++) s += g_part[(bb * 16 + cc) * 10 + c];
            out[t] = s;
        }
    }
}

// ---------------------------------------------------------------------------
extern "C" void kernel_launch(void* const* d_in, const int* in_sizes, int n_in,
                              void* d_out, int out_size)
{
    const float* data = (const float*)d_in[0];
    const float* fW1  = (const float*)d_in[1];
    const float* fb1  = (const float*)d_in[2];
    const float* fW2  = (const float*)d_in[3];
    const float* fb2  = (const float*)d_in[4];
    const float* finW = (const float*)d_in[5];
    const float* finb = (const float*)d_in[6];
    float* out = (float*)d_out;

    cudaFuncSetAttribute(h_kernel,
                         cudaFuncAttributeMaxDynamicSharedMemorySize, H_SMEM);
    cudaFuncSetAttribute(w2_kernel,
                         cudaFuncAttributeMaxDynamicSharedMemorySize, W2_SMEM);

    h_kernel<<<dim3(4, 16, 12), 256, H_SMEM>>>(data, fW1, fb1, fW2, finW);
    w2_kernel<<<dim3(16, 10), 1024, W2_SMEM>>>(fb2);
    recurse_kernel<<<dim3(16, 16), 1024>>>(data, finb, out);
}